// round 15
// baseline (speedup 1.0000x reference)
#include <cuda_runtime.h>

#define WID 512
#define HEI 512
#define NPIX (WID*HEI)
#define RAD 10
#define KS 21
#define TPB 512
#define TSX 32
#define TSY 32
#define TINX 52
#define TINY 52
#define SINP 53                 // padded input tile stride (u64 units; odd -> CF column access)
#define SHP  33                 // padded H-buffer stride (odd -> CF column access)
#define SVP  33                 // V staging stride
#define NTX (WID/TSX)           // 16
#define NTY (HEI/TSY)           // 16
#define NTILES (NTX*NTY)        // 256
#define NELEM (TINY*SINP)       // 2756

// smem layout (bytes) — overlap-packed per phase
#define OFF_IN0   0                       // u64[52*53] = 22048
#define OFF_GRAY  22048                   // float[52*53] = 11024 (PhaseA)
#define OFF_INB   22048                   // u64[52*53] = 22048  (PhaseB second input) -> ends 44096
#define OFF_AH0   33072                   // PhaseA H buffers: u64[52*33] = 13728
#define OFF_AH1   46800
#define OFF_AH2   60528                   // ends 74256
#define OFF_BH0   44096                   // PhaseB H buffers (after INB)
#define OFF_BH1   57824                   // ends 71552
#define OFF_SV    74256                   // V staging: u64[32*33] = 8448
#define SMEM_BYTES 82704

typedef unsigned long long u64;

// ---------------- compile-time weights ----------------
constexpr double cexp(double x) {
    double y = x / 16.0, s = 1.0, t = 1.0;
    for (int i = 1; i < 40; i++) { t *= y / (double)i; s += t; }
    s = s * s; s = s * s; s = s * s; s = s * s;
    return s;
}
constexpr double wgd(int t) { double d = (double)(t - RAD); return cexp(-d * d / 12.5); }
constexpr double wdd(int t) { double d = (double)(t - RAD); return cexp(-d * d * 9.0 / 200.0); }
constexpr double sumw(int wh) { double s = 0; for (int i = 0; i < KS; i++) s += (wh ? wgd(i) : wdd(i)); return s; }
constexpr double pref(int wh, int n) { double s = 0; for (int i = 0; i < n; i++) s += (wh ? wgd(i) : wdd(i)); return s; }

constexpr float SD_F    = (float)sumw(0);
constexpr float SG_F    = (float)sumw(1);
constexpr float SDINV_F = (float)(1.0 / (sumw(0) * sumw(0)));

#define TAPLIST(F) F(0) F(1) F(2) F(3) F(4) F(5) F(6) F(7) F(8) F(9) F(10) \
                   F(11) F(12) F(13) F(14) F(15) F(16) F(17) F(18) F(19) F(20)
#define DWG(i) constexpr float WG_##i = (float)wgd(i);
#define DWD(i) constexpr float WD_##i = (float)wdd(i);
TAPLIST(DWG)
TAPLIST(DWD)

__device__ __forceinline__ float wG(int t) {
    switch (t) {
#define CWG(i) case i: return WG_##i;
        TAPLIST(CWG)
#undef CWG
    }
    return 0.f;
}
__device__ __forceinline__ float wD(int t) {
    switch (t) {
#define CWD(i) case i: return WD_##i;
        TAPLIST(CWD)
#undef CWD
    }
    return 0.f;
}

__constant__ float c_pD[11] = {
    (float)pref(0,0),(float)pref(0,1),(float)pref(0,2),(float)pref(0,3),(float)pref(0,4),
    (float)pref(0,5),(float)pref(0,6),(float)pref(0,7),(float)pref(0,8),(float)pref(0,9),
    (float)pref(0,10)
};
__constant__ float c_pG[11] = {
    (float)pref(1,0),(float)pref(1,1),(float)pref(1,2),(float)pref(1,3),(float)pref(1,4),
    (float)pref(1,5),(float)pref(1,6),(float)pref(1,7),(float)pref(1,8),(float)pref(1,9),
    (float)pref(1,10)
};

__device__ __forceinline__ float hsD(int x) {
    float s = SD_F;
    if (x < RAD) s -= c_pD[RAD - x];
    if (x > WID - 1 - RAD) s -= c_pD[x - (WID - 1 - RAD)];
    return s;
}
__device__ __forceinline__ float hsG(int x) {
    float s = SG_F;
    if (x < RAD) s -= c_pG[RAD - x];
    if (x > WID - 1 - RAD) s -= c_pG[x - (WID - 1 - RAD)];
    return s;
}

// ---------------- packed f32x2 helpers ----------------
__device__ __forceinline__ u64 pk2(float x, float y) {
    u64 r; asm("mov.b64 %0,{%1,%2};" : "=l"(r) : "f"(x), "f"(y)); return r;
}
__device__ __forceinline__ float2 up2(u64 v) {
    float2 o; asm("mov.b64 {%0,%1},%2;" : "=f"(o.x), "=f"(o.y) : "l"(v)); return o;
}
__device__ __forceinline__ void fma2(u64& d, u64 a, u64 b) {
    asm("fma.rn.f32x2 %0,%1,%2,%0;" : "+l"(d) : "l"(a), "l"(b));
}
__device__ __forceinline__ u64 mul2(u64 a, u64 b) {
    u64 r; asm("mul.rn.f32x2 %0,%1,%2;" : "=l"(r) : "l"(a), "l"(b)); return r;
}
__device__ __forceinline__ u64 wpc(float w) {   // (w,w) pair; constant-folds after unroll
    unsigned u = __float_as_uint(w);
    return ((u64)u << 32) | (u64)u;
}

// ---------------- static device planes ----------------
__device__ float g_gray[NPIX], g_mI[NPIX], g_iv[NPIX], g_ibn[NPIX], g_spc[NPIX];
__device__ u64 g_ab1[NPIX];
__device__ u64 g_Qxy[NPIX], g_Qzw[NPIX];
__device__ u64 g_a0[NPIX], g_a1p[NPIX], g_b0[NPIX], g_b1p[NPIX], g_sp0[NPIX], g_sp1[NPIX];

// ---------------- grid barrier ----------------
__device__ unsigned g_count = 0;
__device__ unsigned g_gen   = 0;

__device__ __forceinline__ unsigned gridbar(unsigned gen, int nb) {
    unsigned next = gen + 1;
    __threadfence();
    __syncthreads();
    if (threadIdx.x == 0) {
        if (atomicAdd(&g_count, 1) == (unsigned)(nb - 1)) {
            g_count = 0;
            __threadfence();
            atomicExch(&g_gen, next);
        } else {
            volatile unsigned* ph = &g_gen;
            while (*ph != next) { __nanosleep(40); }
        }
    }
    __syncthreads();
    __threadfence();
    return next;
}

__device__ __forceinline__ float4 softmax4(float4 z) {
    float m = fmaxf(fmaxf(z.x, z.y), fmaxf(z.z, z.w));
    float ex = __expf(z.x - m), ey = __expf(z.y - m);
    float ez = __expf(z.z - m), ew = __expf(z.w - m);
    float inv = 1.f / (ex + ey + ez + ew);
    return make_float4(ex * inv, ey * inv, ez * inv, ew * inv);
}

// division-based tile loader (zero-padded halo)
__device__ __forceinline__ void load_tile(u64* dst, const u64* src,
                                          int X0, int Y0, int tid) {
    for (int s = tid; s < NELEM; s += TPB) {
        int r = s / SINP, c = s - r * SINP;
        int gx = X0 + c - RAD, gy = Y0 + r - RAD;
        u64 v = 0ULL;
        if (c < TINX && (unsigned)gx < WID && (unsigned)gy < HEI) v = src[gy * WID + gx];
        dst[s] = v;
    }
}

// H geometry: 13 warp-tasks cover 52 rows x 8 width-4 chunks
__device__ __forceinline__ void htask_geom(int task, int lane, int& row, int& xb) {
    if (task < 8) { row = lane;                              xb = task * 4; }
    else          { row = 32 + (task - 8) * 4 + (lane >> 3); xb = (lane & 7) * 4; }
}

// ---------------- the persistent kernel ----------------
__global__ void __launch_bounds__(TPB, 2)
k_crf(const float* __restrict__ img, const float4* __restrict__ unary,
      float4* __restrict__ dout, int nb) {
    extern __shared__ char dsm[];
    u64*   sIn  = (u64*)(dsm + OFF_IN0);
    float* sg   = (float*)(dsm + OFF_GRAY);
    u64*   sInB = (u64*)(dsm + OFF_INB);
    u64*   aH0  = (u64*)(dsm + OFF_AH0);
    u64*   aH1  = (u64*)(dsm + OFF_AH1);
    u64*   aH2  = (u64*)(dsm + OFF_AH2);
    u64*   bH0  = (u64*)(dsm + OFF_BH0);
    u64*   bH1  = (u64*)(dsm + OFF_BH1);
    u64*   sV   = (u64*)(dsm + OFF_SV);

    const int tid  = threadIdx.x;
    const int wid  = tid >> 5;
    const int lane = tid & 31;
    const int gid  = blockIdx.x * TPB + tid;
    const int T    = nb * TPB;

    unsigned gen;
    {
        __shared__ unsigned sgen;
        if (tid == 0) sgen = *(volatile unsigned*)&g_gen;
        __syncthreads();
        gen = sgen;
    }

    // ---- P0: grayscale + Q0 = softmax(-unary) ----
    for (int i = gid; i < NPIX; i += T) {
        float r = img[3 * i], gg = img[3 * i + 1], b = img[3 * i + 2];
        g_gray[i] = 0.2989f * r + 0.5870f * gg + 0.1140f * b;
        float4 u = unary[i];
        float4 q = softmax4(make_float4(-u.x, -u.y, -u.z, -u.w));
        g_Qxy[i] = pk2(q.x, q.y);
        g_Qzw[i] = pk2(q.z, q.w);
    }
    gen = gridbar(gen, nb);

    // ---- PreA: conv2D of (gray, gray^2) -> mI, iv, (a1,b1) ----
    for (int t = blockIdx.x; t < NTILES; t += nb) {
        int X0 = (t & (NTX - 1)) * TSX, Y0 = (t >> 4) * TSY;
        for (int s = tid; s < NELEM; s += TPB) {
            int r = s / SINP, c = s - r * SINP;
            int gx = X0 + c - RAD, gy = Y0 + r - RAD;
            u64 v = 0ULL;
            if (c < TINX && (unsigned)gx < WID && (unsigned)gy < HEI) {
                float gv = g_gray[gy * WID + gx];
                v = pk2(gv, gv * gv);
            }
            sIn[s] = v;
        }
        __syncthreads();
        if (wid < 13) {
            int row, xb; htask_geom(wid, lane, row, xb);
            u64 a[4] = {0,0,0,0};
            const u64* rw = sIn + row * SINP + xb;
#pragma unroll
            for (int tt = 0; tt < 24; tt++) {
                u64 v = rw[tt];
#pragma unroll
                for (int m = 0; m < 4; m++) {
                    int w = tt - m;
                    if (w >= 0 && w < KS) fma2(a[m], v, wpc(wD(w)));
                }
            }
#pragma unroll
            for (int m = 0; m < 4; m++) aH0[row * SHP + xb + m] = a[m];
        }
        __syncthreads();
        if (wid < 8) {
            int py0 = wid * 4;
            u64 A[4] = {0,0,0,0};
#pragma unroll
            for (int j = 0; j < 24; j++) {
                u64 v = aH0[(py0 + j) * SHP + lane];
#pragma unroll
                for (int m = 0; m < 4; m++) {
                    int w = j - m;
                    if (w >= 0 && w < KS) fma2(A[m], v, wpc(wD(w)));
                }
            }
            float hdx = hsD(X0 + lane);
#pragma unroll
            for (int m = 0; m < 4; m++) {
                int py = py0 + m, gy = Y0 + py, idx = gy * WID + X0 + lane;
                float2 c = up2(A[m]);
                float g = up2(sIn[(py + RAD) * SINP + lane + RAD]).x;
                float mI  = (c.x - g) * SDINV_F;
                float mII = (c.y - g * g) * SDINV_F;
                float mp1 = (hdx * hsD(gy) - 1.f) * SDINV_F;
                float var = mII - mI * mI;
                float iv  = 1.f / (var + 1e-4f);
                float a1  = mI * (1.f - mp1) * iv;
                float b1  = mp1 - a1 * mI;
                g_mI[idx] = mI; g_iv[idx] = iv; g_ab1[idx] = pk2(a1, b1);
            }
        }
        __syncthreads();
    }
    gen = gridbar(gen, nb);

    // ---- PreB: conv2D of (a1,b1) -> ibn, spc ----
    for (int t = blockIdx.x; t < NTILES; t += nb) {
        int X0 = (t & (NTX - 1)) * TSX, Y0 = (t >> 4) * TSY;
        load_tile(sIn, g_ab1, X0, Y0, tid);
        __syncthreads();
        if (wid < 13) {
            int row, xb; htask_geom(wid, lane, row, xb);
            u64 a[4] = {0,0,0,0};
            const u64* rw = sIn + row * SINP + xb;
#pragma unroll
            for (int tt = 0; tt < 24; tt++) {
                u64 v = rw[tt];
#pragma unroll
                for (int m = 0; m < 4; m++) {
                    int w = tt - m;
                    if (w >= 0 && w < KS) fma2(a[m], v, wpc(wD(w)));
                }
            }
#pragma unroll
            for (int m = 0; m < 4; m++) aH0[row * SHP + xb + m] = a[m];
        }
        __syncthreads();
        if (wid < 8) {
            int py0 = wid * 4;
            u64 A[4] = {0,0,0,0};
#pragma unroll
            for (int j = 0; j < 24; j++) {
                u64 v = aH0[(py0 + j) * SHP + lane];
#pragma unroll
                for (int m = 0; m < 4; m++) {
                    int w = j - m;
                    if (w >= 0 && w < KS) fma2(A[m], v, wpc(wD(w)));
                }
            }
            float hgx = hsG(X0 + lane);
#pragma unroll
            for (int m = 0; m < 4; m++) {
                int py = py0 + m, gy = Y0 + py, idx = gy * WID + X0 + lane;
                float2 c  = up2(A[m]);
                float2 ab = up2(sIn[(py + RAD) * SINP + lane + RAD]);
                float g = g_gray[idx];
                float gfa = (c.x - ab.x) * SDINV_F;
                float gfb = (c.y - ab.y) * SDINV_F;
                g_ibn[idx] = 10.f / (gfa * g + gfb);
                g_spc[idx] = 3.f / (hgx * hsG(gy) - 1.f);
            }
        }
        __syncthreads();
    }
    gen = gridbar(gen, nb);

    // ---- 5 mean-field iterations: 2 tiled phases each ----
    for (int it = 0; it < 5; it++) {
        // ===== PhaseA: conv2D(Q)x{G,D} + conv2D(grayQ)xD -> a,b,sp =====
        for (int t = blockIdx.x; t < NTILES; t += nb) {
            int X0 = (t & (NTX - 1)) * TSX, Y0 = (t >> 4) * TSY;
            for (int s = tid; s < NELEM; s += TPB) {
                int r = s / SINP, c = s - r * SINP;
                int gx = X0 + c - RAD, gy = Y0 + r - RAD;
                float v = 0.f;
                if (c < TINX && (unsigned)gx < WID && (unsigned)gy < HEI) v = g_gray[gy * WID + gx];
                sg[s] = v;
            }
            for (int h = 0; h < 2; h++) {
                load_tile(sIn, h ? g_Qzw : g_Qxy, X0, Y0, tid);
                __syncthreads();
                if (wid < 13) {
                    int row, xb; htask_geom(wid, lane, row, xb);
                    u64 aD[4] = {0,0,0,0}, aG[4] = {0,0,0,0}, aI[4] = {0,0,0,0};
                    const u64*  rw = sIn + row * SINP + xb;
                    const float* rg = sg + row * SINP + xb;
#pragma unroll
                    for (int tt = 0; tt < 24; tt++) {
                        u64 v = rw[tt];
                        float gf = rg[tt];
                        u64 wv = mul2(v, pk2(gf, gf));
#pragma unroll
                        for (int m = 0; m < 4; m++) {
                            int w = tt - m;
                            if (w >= 0 && w < KS) {
                                fma2(aD[m], v,  wpc(wD(w)));
                                fma2(aG[m], v,  wpc(wG(w)));
                                fma2(aI[m], wv, wpc(wD(w)));
                            }
                        }
                    }
#pragma unroll
                    for (int m = 0; m < 4; m++) {
                        aH0[row * SHP + xb + m] = aD[m];
                        aH1[row * SHP + xb + m] = aG[m];
                        aH2[row * SHP + xb + m] = aI[m];
                    }
                }
                __syncthreads();
                // --- split V across all 16 warps: 0-7 -> D+G ; 8-15 -> I (staged) ---
                int py0 = (wid & 7) * 4;
                u64 AD[4] = {0,0,0,0}, AG[4] = {0,0,0,0};
                if (wid < 8) {
#pragma unroll
                    for (int j = 0; j < 24; j++) {
                        u64 v0 = aH0[(py0 + j) * SHP + lane];
                        u64 v1 = aH1[(py0 + j) * SHP + lane];
#pragma unroll
                        for (int m = 0; m < 4; m++) {
                            int w = j - m;
                            if (w >= 0 && w < KS) {
                                fma2(AD[m], v0, wpc(wD(w)));
                                fma2(AG[m], v1, wpc(wG(w)));
                            }
                        }
                    }
                } else {
                    u64 AI[4] = {0,0,0,0};
#pragma unroll
                    for (int j = 0; j < 24; j++) {
                        u64 v2 = aH2[(py0 + j) * SHP + lane];
#pragma unroll
                        for (int m = 0; m < 4; m++) {
                            int w = j - m;
                            if (w >= 0 && w < KS) fma2(AI[m], v2, wpc(wD(w)));
                        }
                    }
#pragma unroll
                    for (int m = 0; m < 4; m++) sV[(py0 + m) * SVP + lane] = AI[m];
                }
                __syncthreads();
                if (wid < 8) {
#pragma unroll
                    for (int m = 0; m < 4; m++) {
                        int py = py0 + m, idx = (Y0 + py) * WID + X0 + lane;
                        float2 q = up2(sIn[(py + RAD) * SINP + lane + RAD]);
                        float g = sg[(py + RAD) * SINP + lane + RAD];
                        float2 ad = up2(AD[m]), ag = up2(AG[m]);
                        float2 ai = up2(sV[py * SVP + lane]);
                        float mI = g_mI[idx], iv = g_iv[idx], spc = g_spc[idx];
                        float spx = (ag.x - q.x) * spc,         spy = (ag.y - q.y) * spc;
                        float mpx = (ad.x - q.x) * SDINV_F,     mpy = (ad.y - q.y) * SDINV_F;
                        float mix = (ai.x - g * q.x) * SDINV_F, miy = (ai.y - g * q.y) * SDINV_F;
                        float ax = (mix - mI * mpx) * iv,       ay = (miy - mI * mpy) * iv;
                        float bx = mpx - ax * mI,               by = mpy - ay * mI;
                        if (h == 0) {
                            g_a0[idx]  = pk2(ax, ay);
                            g_b0[idx]  = pk2(bx, by);
                            g_sp0[idx] = pk2(spx, spy);
                        } else {
                            g_a1p[idx] = pk2(ax, ay);
                            g_b1p[idx] = pk2(bx, by);
                            g_sp1[idx] = pk2(spx, spy);
                        }
                    }
                }
                __syncthreads();
            }
        }
        gen = gridbar(gen, nb);

        // ===== PhaseB: conv2D(a,b) + message + softmax -> Q / dout =====
        for (int t = blockIdx.x; t < NTILES; t += nb) {
            int X0 = (t & (NTX - 1)) * TSX, Y0 = (t >> 4) * TSY;
            float z0[8];
            for (int h = 0; h < 2; h++) {
                load_tile(sIn,  h ? g_a1p : g_a0, X0, Y0, tid);
                load_tile(sInB, h ? g_b1p : g_b0, X0, Y0, tid);
                __syncthreads();
                if (wid < 13) {
                    int row, xb; htask_geom(wid, lane, row, xb);
                    u64 aA[4] = {0,0,0,0}, aB[4] = {0,0,0,0};
                    const u64* rwA = sIn  + row * SINP + xb;
                    const u64* rwB = sInB + row * SINP + xb;
#pragma unroll
                    for (int tt = 0; tt < 24; tt++) {
                        u64 vA = rwA[tt], vB = rwB[tt];
#pragma unroll
                        for (int m = 0; m < 4; m++) {
                            int w = tt - m;
                            if (w >= 0 && w < KS) {
                                fma2(aA[m], vA, wpc(wD(w)));
                                fma2(aB[m], vB, wpc(wD(w)));
                            }
                        }
                    }
#pragma unroll
                    for (int m = 0; m < 4; m++) {
                        bH0[row * SHP + xb + m] = aA[m];
                        bH1[row * SHP + xb + m] = aB[m];
                    }
                }
                __syncthreads();
                // --- split V across all 16 warps: 0-7 -> A ; 8-15 -> B (staged) ---
                int py0 = (wid & 7) * 4;
                u64 AA[4] = {0,0,0,0};
                if (wid < 8) {
#pragma unroll
                    for (int j = 0; j < 24; j++) {
                        u64 v0 = bH0[(py0 + j) * SHP + lane];
#pragma unroll
                        for (int m = 0; m < 4; m++) {
                            int w = j - m;
                            if (w >= 0 && w < KS) fma2(AA[m], v0, wpc(wD(w)));
                        }
                    }
                } else {
                    u64 AB[4] = {0,0,0,0};
#pragma unroll
                    for (int j = 0; j < 24; j++) {
                        u64 v1 = bH1[(py0 + j) * SHP + lane];
#pragma unroll
                        for (int m = 0; m < 4; m++) {
                            int w = j - m;
                            if (w >= 0 && w < KS) fma2(AB[m], v1, wpc(wD(w)));
                        }
                    }
#pragma unroll
                    for (int m = 0; m < 4; m++) sV[(py0 + m) * SVP + lane] = AB[m];
                }
                __syncthreads();
                if (wid < 8) {
#pragma unroll
                    for (int m = 0; m < 4; m++) {
                        int py = py0 + m, idx = (Y0 + py) * WID + X0 + lane;
                        float2 ac = up2(sIn [(py + RAD) * SINP + lane + RAD]);
                        float2 bc = up2(sInB[(py + RAD) * SINP + lane + RAD]);
                        float2 aa = up2(AA[m]);
                        float2 ab = up2(sV[py * SVP + lane]);
                        float2 sp = up2(h ? g_sp1[idx] : g_sp0[idx]);
                        float ibn = g_ibn[idx], g = g_gray[idx];
                        float2 uu = *((const float2*)unary + 2 * idx + h);
                        float zx = sp.x + ((aa.x - ac.x) * SDINV_F * g
                                         + (ab.x - bc.x) * SDINV_F) * ibn - uu.x;
                        float zy = sp.y + ((aa.y - ac.y) * SDINV_F * g
                                         + (ab.y - bc.y) * SDINV_F) * ibn - uu.y;
                        if (h == 0) {
                            z0[2*m] = zx; z0[2*m+1] = zy;
                        } else {
                            float4 q = softmax4(make_float4(z0[2*m], z0[2*m+1], zx, zy));
                            if (it == 4) {
                                dout[idx] = q;
                            } else {
                                g_Qxy[idx] = pk2(q.x, q.y);
                                g_Qzw[idx] = pk2(q.z, q.w);
                            }
                        }
                    }
                }
                __syncthreads();
            }
        }
        if (it < 4) gen = gridbar(gen, nb);
    }
}

// ---------------- launch ----------------
extern "C" void kernel_launch(void* const* d_in, const int* in_sizes, int n_in,
                              void* d_out, int out_size) {
    const float* unary = nullptr;
    const float* image = nullptr;
    for (int i = 0; i < n_in; i++) {
        if (in_sizes[i] == NPIX * 4) unary = (const float*)d_in[i];
        else if (in_sizes[i] == NPIX * 3) image = (const float*)d_in[i];
    }

    cudaFuncSetAttribute(k_crf, cudaFuncAttributeMaxDynamicSharedMemorySize, SMEM_BYTES);

    int sms = 0, occ = 0;
    cudaDeviceGetAttribute(&sms, cudaDevAttrMultiProcessorCount, 0);
    cudaOccupancyMaxActiveBlocksPerMultiprocessor(&occ, k_crf, TPB, SMEM_BYTES);
    if (sms <= 0) sms = 148;
    if (occ <= 0) occ = 1;
    int nb = sms * occ;
    if (nb > 1024) nb = 1024;

    k_crf<<<nb, TPB, SMEM_BYTES>>>(image, (const float4*)unary, (float4*)d_out, nb);
}

// round 16
// speedup vs baseline: 1.1654x; 1.1654x over previous
#include <cuda_runtime.h>

#define WID 512
#define HEI 512
#define NPIX (WID*HEI)
#define RAD 10
#define KS 21
#define TPB 256
#define TSX 32
#define TSY 16
#define TINX 52
#define TINY 36
#define SINP 53                 // padded input tile stride (u64 units; odd -> CF column access)
#define SHP  33                 // padded H-buffer stride (odd -> CF column access)
#define NTX (WID/TSX)           // 16
#define NTY (HEI/TSY)           // 32
#define NTILES (NTX*NTY)        // 512
#define NELEM (TINY*SINP)       // 1908

// smem layout (bytes) — overlap-packed per phase
#define OFF_IN0   0                       // u64[36*53] = 15264
#define OFF_GRAY  15264                   // float[36*53] = 7632  (PhaseA)
#define OFF_INB   15264                   // u64 tile (PhaseB second input)
#define OFF_AH0   22896                   // H buffers: u64[36*33] = 9504
#define OFF_AH1   32400
#define OFF_AH2   41904
#define OFF_BH0   30528
#define OFF_BH1   40032
#define SMEM_BYTES 51408

typedef unsigned long long u64;

// ---------------- compile-time weights ----------------
constexpr double cexp(double x) {
    double y = x / 16.0, s = 1.0, t = 1.0;
    for (int i = 1; i < 40; i++) { t *= y / (double)i; s += t; }
    s = s * s; s = s * s; s = s * s; s = s * s;
    return s;
}
constexpr double wgd(int t) { double d = (double)(t - RAD); return cexp(-d * d / 12.5); }
constexpr double wdd(int t) { double d = (double)(t - RAD); return cexp(-d * d * 9.0 / 200.0); }
constexpr double sumw(int wh) { double s = 0; for (int i = 0; i < KS; i++) s += (wh ? wgd(i) : wdd(i)); return s; }
constexpr double pref(int wh, int n) { double s = 0; for (int i = 0; i < n; i++) s += (wh ? wgd(i) : wdd(i)); return s; }

constexpr float SD_F    = (float)sumw(0);
constexpr float SG_F    = (float)sumw(1);
constexpr float SDINV_F = (float)(1.0 / (sumw(0) * sumw(0)));

#define TAPLIST(F) F(0) F(1) F(2) F(3) F(4) F(5) F(6) F(7) F(8) F(9) F(10) \
                   F(11) F(12) F(13) F(14) F(15) F(16) F(17) F(18) F(19) F(20)
#define DWG(i) constexpr float WG_##i = (float)wgd(i);
#define DWD(i) constexpr float WD_##i = (float)wdd(i);
TAPLIST(DWG)
TAPLIST(DWD)

__device__ __forceinline__ float wG(int t) {
    switch (t) {
#define CWG(i) case i: return WG_##i;
        TAPLIST(CWG)
#undef CWG
    }
    return 0.f;
}
__device__ __forceinline__ float wD(int t) {
    switch (t) {
#define CWD(i) case i: return WD_##i;
        TAPLIST(CWD)
#undef CWD
    }
    return 0.f;
}

__constant__ float c_pD[11] = {
    (float)pref(0,0),(float)pref(0,1),(float)pref(0,2),(float)pref(0,3),(float)pref(0,4),
    (float)pref(0,5),(float)pref(0,6),(float)pref(0,7),(float)pref(0,8),(float)pref(0,9),
    (float)pref(0,10)
};
__constant__ float c_pG[11] = {
    (float)pref(1,0),(float)pref(1,1),(float)pref(1,2),(float)pref(1,3),(float)pref(1,4),
    (float)pref(1,5),(float)pref(1,6),(float)pref(1,7),(float)pref(1,8),(float)pref(1,9),
    (float)pref(1,10)
};

__device__ __forceinline__ float hsD(int x) {
    float s = SD_F;
    if (x < RAD) s -= c_pD[RAD - x];
    if (x > WID - 1 - RAD) s -= c_pD[x - (WID - 1 - RAD)];
    return s;
}
__device__ __forceinline__ float hsG(int x) {
    float s = SG_F;
    if (x < RAD) s -= c_pG[RAD - x];
    if (x > WID - 1 - RAD) s -= c_pG[x - (WID - 1 - RAD)];
    return s;
}

// ---------------- packed f32x2 helpers ----------------
__device__ __forceinline__ u64 pk2(float x, float y) {
    u64 r; asm("mov.b64 %0,{%1,%2};" : "=l"(r) : "f"(x), "f"(y)); return r;
}
__device__ __forceinline__ float2 up2(u64 v) {
    float2 o; asm("mov.b64 {%0,%1},%2;" : "=f"(o.x), "=f"(o.y) : "l"(v)); return o;
}
__device__ __forceinline__ void fma2(u64& d, u64 a, u64 b) {
    asm("fma.rn.f32x2 %0,%1,%2,%0;" : "+l"(d) : "l"(a), "l"(b));
}
__device__ __forceinline__ u64 mul2(u64 a, u64 b) {
    u64 r; asm("mul.rn.f32x2 %0,%1,%2;" : "=l"(r) : "l"(a), "l"(b)); return r;
}
__device__ __forceinline__ u64 wpc(float w) {   // (w,w) pair; constant-folds after unroll
    unsigned u = __float_as_uint(w);
    return ((u64)u << 32) | (u64)u;
}

// ---------------- static device planes ----------------
__device__ float g_gray[NPIX], g_mI[NPIX], g_iv[NPIX], g_ibn[NPIX], g_spc[NPIX];
__device__ u64 g_ab1[NPIX];
__device__ u64 g_Qxy[NPIX], g_Qzw[NPIX];
__device__ u64 g_a0[NPIX], g_a1p[NPIX], g_b0[NPIX], g_b1p[NPIX], g_sp0[NPIX], g_sp1[NPIX];

// ---------------- grid barrier ----------------
__device__ unsigned g_count = 0;
__device__ unsigned g_gen   = 0;

// CG-style grid barrier: one elected thread per block carries the
// release/acquire fences (bar.sync cumulativity covers the CTA's writes;
// the single acquire-side CCTL.IVALL invalidates the SM-shared L1 for all
// threads parked at the trailing __syncthreads).
__device__ __forceinline__ unsigned gridbar(unsigned gen, int nb) {
    unsigned next = gen + 1;
    __syncthreads();
    if (threadIdx.x == 0) {
        __threadfence();   // release (block's prior writes -> L2)
        if (atomicAdd(&g_count, 1) == (unsigned)(nb - 1)) {
            g_count = 0;
            atomicExch(&g_gen, next);
        } else {
            volatile unsigned* ph = &g_gen;
            while (*ph != next) { __nanosleep(128); }
        }
        __threadfence();   // acquire (invalidate this SM's L1)
    }
    __syncthreads();
    return next;
}

__device__ __forceinline__ float4 softmax4(float4 z) {
    float m = fmaxf(fmaxf(z.x, z.y), fmaxf(z.z, z.w));
    float ex = __expf(z.x - m), ey = __expf(z.y - m);
    float ez = __expf(z.z - m), ew = __expf(z.w - m);
    float inv = 1.f / (ex + ey + ez + ew);
    return make_float4(ex * inv, ey * inv, ez * inv, ew * inv);
}

// division-based tile loader (zero-padded halo)
__device__ __forceinline__ void load_tile(u64* dst, const u64* src,
                                          int X0, int Y0, int tid) {
    for (int s = tid; s < NELEM; s += TPB) {
        int r = s / SINP, c = s - r * SINP;
        int gx = X0 + c - RAD, gy = Y0 + r - RAD;
        u64 v = 0ULL;
        if (c < TINX && (unsigned)gx < WID && (unsigned)gy < HEI) v = src[gy * WID + gx];
        dst[s] = v;
    }
}

// H task geometry: tasks 0..7 = column chunk (xb=task*4), rows = lane (0..31).
// task 8 = tail rows 32..35: lane = (row-32)*8 + chunk.
__device__ __forceinline__ void htask_geom(int task, int lane, int& row, int& xb) {
    if (task < 8) { row = lane;              xb = task * 4; }
    else          { row = 32 + (lane >> 3);  xb = (lane & 7) * 4; }
}

// ---------------- the persistent kernel ----------------
__global__ void __launch_bounds__(TPB, 4)
k_crf(const float* __restrict__ img, const float4* __restrict__ unary,
      float4* __restrict__ dout, int nb) {
    extern __shared__ char dsm[];
    u64*   sIn  = (u64*)(dsm + OFF_IN0);
    float* sg   = (float*)(dsm + OFF_GRAY);
    u64*   sInB = (u64*)(dsm + OFF_INB);
    u64*   aH0  = (u64*)(dsm + OFF_AH0);
    u64*   aH1  = (u64*)(dsm + OFF_AH1);
    u64*   aH2  = (u64*)(dsm + OFF_AH2);
    u64*   bH0  = (u64*)(dsm + OFF_BH0);
    u64*   bH1  = (u64*)(dsm + OFF_BH1);

    const int tid  = threadIdx.x;
    const int wid  = tid >> 5;
    const int lane = tid & 31;
    const int gid  = blockIdx.x * TPB + tid;
    const int T    = nb * TPB;

    unsigned gen;
    {
        __shared__ unsigned sgen;
        if (tid == 0) sgen = *(volatile unsigned*)&g_gen;
        __syncthreads();
        gen = sgen;
    }

    // ---- P0: grayscale + Q0 = softmax(-unary) ----
    for (int i = gid; i < NPIX; i += T) {
        float r = img[3 * i], gg = img[3 * i + 1], b = img[3 * i + 2];
        g_gray[i] = 0.2989f * r + 0.5870f * gg + 0.1140f * b;
        float4 u = unary[i];
        float4 q = softmax4(make_float4(-u.x, -u.y, -u.z, -u.w));
        g_Qxy[i] = pk2(q.x, q.y);
        g_Qzw[i] = pk2(q.z, q.w);
    }
    gen = gridbar(gen, nb);

    // ---- PreA: conv2D of (gray, gray^2) -> mI, iv, (a1,b1) ----
    for (int t = blockIdx.x; t < NTILES; t += nb) {
        int X0 = (t & (NTX - 1)) * TSX, Y0 = (t >> 4) * TSY;
        for (int s = tid; s < NELEM; s += TPB) {
            int r = s / SINP, c = s - r * SINP;
            int gx = X0 + c - RAD, gy = Y0 + r - RAD;
            u64 v = 0ULL;
            if (c < TINX && (unsigned)gx < WID && (unsigned)gy < HEI) {
                float gv = g_gray[gy * WID + gx];
                v = pk2(gv, gv * gv);
            }
            sIn[s] = v;
        }
        __syncthreads();
        for (int task = wid; task < 9; task += 8) {
            int row, xb; htask_geom(task, lane, row, xb);
            u64 a[4] = {0,0,0,0};
            const u64* rw = sIn + row * SINP + xb;
#pragma unroll
            for (int tt = 0; tt < 24; tt++) {
                u64 v = rw[tt];
#pragma unroll
                for (int m = 0; m < 4; m++) {
                    int w = tt - m;
                    if (w >= 0 && w < KS) fma2(a[m], v, wpc(wD(w)));
                }
            }
#pragma unroll
            for (int m = 0; m < 4; m++) aH0[row * SHP + xb + m] = a[m];
        }
        __syncthreads();
        if (wid < 4) {
            int py0 = wid * 4;
            u64 A[4] = {0,0,0,0};
#pragma unroll
            for (int j = 0; j < 24; j++) {
                u64 v = aH0[(py0 + j) * SHP + lane];
#pragma unroll
                for (int m = 0; m < 4; m++) {
                    int w = j - m;
                    if (w >= 0 && w < KS) fma2(A[m], v, wpc(wD(w)));
                }
            }
            float hdx = hsD(X0 + lane);
#pragma unroll
            for (int m = 0; m < 4; m++) {
                int py = py0 + m, gy = Y0 + py, idx = gy * WID + X0 + lane;
                float2 c = up2(A[m]);
                float g = up2(sIn[(py + RAD) * SINP + lane + RAD]).x;
                float mI  = (c.x - g) * SDINV_F;
                float mII = (c.y - g * g) * SDINV_F;
                float mp1 = (hdx * hsD(gy) - 1.f) * SDINV_F;
                float var = mII - mI * mI;
                float iv  = 1.f / (var + 1e-4f);
                float a1  = mI * (1.f - mp1) * iv;
                float b1  = mp1 - a1 * mI;
                g_mI[idx] = mI; g_iv[idx] = iv; g_ab1[idx] = pk2(a1, b1);
            }
        }
        __syncthreads();
    }
    gen = gridbar(gen, nb);

    // ---- PreB: conv2D of (a1,b1) -> ibn, spc ----
    for (int t = blockIdx.x; t < NTILES; t += nb) {
        int X0 = (t & (NTX - 1)) * TSX, Y0 = (t >> 4) * TSY;
        load_tile(sIn, g_ab1, X0, Y0, tid);
        __syncthreads();
        for (int task = wid; task < 9; task += 8) {
            int row, xb; htask_geom(task, lane, row, xb);
            u64 a[4] = {0,0,0,0};
            const u64* rw = sIn + row * SINP + xb;
#pragma unroll
            for (int tt = 0; tt < 24; tt++) {
                u64 v = rw[tt];
#pragma unroll
                for (int m = 0; m < 4; m++) {
                    int w = tt - m;
                    if (w >= 0 && w < KS) fma2(a[m], v, wpc(wD(w)));
                }
            }
#pragma unroll
            for (int m = 0; m < 4; m++) aH0[row * SHP + xb + m] = a[m];
        }
        __syncthreads();
        if (wid < 4) {
            int py0 = wid * 4;
            u64 A[4] = {0,0,0,0};
#pragma unroll
            for (int j = 0; j < 24; j++) {
                u64 v = aH0[(py0 + j) * SHP + lane];
#pragma unroll
                for (int m = 0; m < 4; m++) {
                    int w = j - m;
                    if (w >= 0 && w < KS) fma2(A[m], v, wpc(wD(w)));
                }
            }
            float hgx = hsG(X0 + lane);
#pragma unroll
            for (int m = 0; m < 4; m++) {
                int py = py0 + m, gy = Y0 + py, idx = gy * WID + X0 + lane;
                float2 c  = up2(A[m]);
                float2 ab = up2(sIn[(py + RAD) * SINP + lane + RAD]);
                float g = g_gray[idx];
                float gfa = (c.x - ab.x) * SDINV_F;
                float gfb = (c.y - ab.y) * SDINV_F;
                g_ibn[idx] = 10.f / (gfa * g + gfb);
                g_spc[idx] = 3.f / (hgx * hsG(gy) - 1.f);
            }
        }
        __syncthreads();
    }
    gen = gridbar(gen, nb);

    // ---- 5 mean-field iterations: 2 tiled phases each ----
    for (int it = 0; it < 5; it++) {
        // ===== PhaseA: conv2D(Q)x{G,D} + conv2D(grayQ)xD -> a,b,sp =====
        for (int t = blockIdx.x; t < NTILES; t += nb) {
            int X0 = (t & (NTX - 1)) * TSX, Y0 = (t >> 4) * TSY;
            for (int s = tid; s < NELEM; s += TPB) {
                int r = s / SINP, c = s - r * SINP;
                int gx = X0 + c - RAD, gy = Y0 + r - RAD;
                float v = 0.f;
                if (c < TINX && (unsigned)gx < WID && (unsigned)gy < HEI) v = g_gray[gy * WID + gx];
                sg[s] = v;
            }
            for (int h = 0; h < 2; h++) {
                load_tile(sIn, h ? g_Qzw : g_Qxy, X0, Y0, tid);
                __syncthreads();
                for (int task = wid; task < 9; task += 8) {
                    int row, xb; htask_geom(task, lane, row, xb);
                    u64 aD[4] = {0,0,0,0}, aG[4] = {0,0,0,0}, aI[4] = {0,0,0,0};
                    const u64*  rw = sIn + row * SINP + xb;
                    const float* rg = sg + row * SINP + xb;
#pragma unroll
                    for (int tt = 0; tt < 24; tt++) {
                        u64 v = rw[tt];
                        float gf = rg[tt];
                        u64 wv = mul2(v, pk2(gf, gf));
#pragma unroll
                        for (int m = 0; m < 4; m++) {
                            int w = tt - m;
                            if (w >= 0 && w < KS) {
                                fma2(aD[m], v,  wpc(wD(w)));
                                fma2(aG[m], v,  wpc(wG(w)));
                                fma2(aI[m], wv, wpc(wD(w)));
                            }
                        }
                    }
#pragma unroll
                    for (int m = 0; m < 4; m++) {
                        aH0[row * SHP + xb + m] = aD[m];
                        aH1[row * SHP + xb + m] = aG[m];
                        aH2[row * SHP + xb + m] = aI[m];
                    }
                }
                __syncthreads();
                if (wid < 4) {
                    int py0 = wid * 4;
                    u64 AD[4] = {0,0,0,0}, AG[4] = {0,0,0,0}, AI[4] = {0,0,0,0};
#pragma unroll
                    for (int j = 0; j < 24; j++) {
                        u64 v0 = aH0[(py0 + j) * SHP + lane];
                        u64 v1 = aH1[(py0 + j) * SHP + lane];
                        u64 v2 = aH2[(py0 + j) * SHP + lane];
#pragma unroll
                        for (int m = 0; m < 4; m++) {
                            int w = j - m;
                            if (w >= 0 && w < KS) {
                                fma2(AD[m], v0, wpc(wD(w)));
                                fma2(AG[m], v1, wpc(wG(w)));
                                fma2(AI[m], v2, wpc(wD(w)));
                            }
                        }
                    }
#pragma unroll
                    for (int m = 0; m < 4; m++) {
                        int py = py0 + m, idx = (Y0 + py) * WID + X0 + lane;
                        float2 q = up2(sIn[(py + RAD) * SINP + lane + RAD]);
                        float g = sg[(py + RAD) * SINP + lane + RAD];
                        float2 ad = up2(AD[m]), ag = up2(AG[m]), ai = up2(AI[m]);
                        float mI = g_mI[idx], iv = g_iv[idx], spc = g_spc[idx];
                        float spx = (ag.x - q.x) * spc,         spy = (ag.y - q.y) * spc;
                        float mpx = (ad.x - q.x) * SDINV_F,     mpy = (ad.y - q.y) * SDINV_F;
                        float mix = (ai.x - g * q.x) * SDINV_F, miy = (ai.y - g * q.y) * SDINV_F;
                        float ax = (mix - mI * mpx) * iv,       ay = (miy - mI * mpy) * iv;
                        float bx = mpx - ax * mI,               by = mpy - ay * mI;
                        if (h == 0) {
                            g_a0[idx]  = pk2(ax, ay);
                            g_b0[idx]  = pk2(bx, by);
                            g_sp0[idx] = pk2(spx, spy);
                        } else {
                            g_a1p[idx] = pk2(ax, ay);
                            g_b1p[idx] = pk2(bx, by);
                            g_sp1[idx] = pk2(spx, spy);
                        }
                    }
                }
                __syncthreads();
            }
        }
        gen = gridbar(gen, nb);

        // ===== PhaseB: conv2D(a,b) + message + softmax -> Q / dout =====
        for (int t = blockIdx.x; t < NTILES; t += nb) {
            int X0 = (t & (NTX - 1)) * TSX, Y0 = (t >> 4) * TSY;
            float z0[8];
            for (int h = 0; h < 2; h++) {
                load_tile(sIn,  h ? g_a1p : g_a0, X0, Y0, tid);
                load_tile(sInB, h ? g_b1p : g_b0, X0, Y0, tid);
                __syncthreads();
                for (int task = wid; task < 9; task += 8) {
                    int row, xb; htask_geom(task, lane, row, xb);
                    u64 aA[4] = {0,0,0,0}, aB[4] = {0,0,0,0};
                    const u64* rwA = sIn  + row * SINP + xb;
                    const u64* rwB = sInB + row * SINP + xb;
#pragma unroll
                    for (int tt = 0; tt < 24; tt++) {
                        u64 vA = rwA[tt], vB = rwB[tt];
#pragma unroll
                        for (int m = 0; m < 4; m++) {
                            int w = tt - m;
                            if (w >= 0 && w < KS) {
                                fma2(aA[m], vA, wpc(wD(w)));
                                fma2(aB[m], vB, wpc(wD(w)));
                            }
                        }
                    }
#pragma unroll
                    for (int m = 0; m < 4; m++) {
                        bH0[row * SHP + xb + m] = aA[m];
                        bH1[row * SHP + xb + m] = aB[m];
                    }
                }
                __syncthreads();
                if (wid < 4) {
                    int py0 = wid * 4;
                    u64 AA[4] = {0,0,0,0}, AB[4] = {0,0,0,0};
#pragma unroll
                    for (int j = 0; j < 24; j++) {
                        u64 v0 = bH0[(py0 + j) * SHP + lane];
                        u64 v1 = bH1[(py0 + j) * SHP + lane];
#pragma unroll
                        for (int m = 0; m < 4; m++) {
                            int w = j - m;
                            if (w >= 0 && w < KS) {
                                fma2(AA[m], v0, wpc(wD(w)));
                                fma2(AB[m], v1, wpc(wD(w)));
                            }
                        }
                    }
#pragma unroll
                    for (int m = 0; m < 4; m++) {
                        int py = py0 + m, idx = (Y0 + py) * WID + X0 + lane;
                        float2 ac = up2(sIn [(py + RAD) * SINP + lane + RAD]);
                        float2 bc = up2(sInB[(py + RAD) * SINP + lane + RAD]);
                        float2 aa = up2(AA[m]), ab = up2(AB[m]);
                        float2 sp = up2(h ? g_sp1[idx] : g_sp0[idx]);
                        float ibn = g_ibn[idx], g = g_gray[idx];
                        float2 uu = *((const float2*)unary + 2 * idx + h);
                        float zx = sp.x + ((aa.x - ac.x) * SDINV_F * g
                                         + (ab.x - bc.x) * SDINV_F) * ibn - uu.x;
                        float zy = sp.y + ((aa.y - ac.y) * SDINV_F * g
                                         + (ab.y - bc.y) * SDINV_F) * ibn - uu.y;
                        if (h == 0) {
                            z0[2*m] = zx; z0[2*m+1] = zy;
                        } else {
                            float4 q = softmax4(make_float4(z0[2*m], z0[2*m+1], zx, zy));
                            if (it == 4) {
                                dout[idx] = q;
                            } else {
                                g_Qxy[idx] = pk2(q.x, q.y);
                                g_Qzw[idx] = pk2(q.z, q.w);
                            }
                        }
                    }
                }
                __syncthreads();
            }
        }
        if (it < 4) gen = gridbar(gen, nb);
    }
}

// ---------------- launch ----------------
extern "C" void kernel_launch(void* const* d_in, const int* in_sizes, int n_in,
                              void* d_out, int out_size) {
    const float* unary = nullptr;
    const float* image = nullptr;
    for (int i = 0; i < n_in; i++) {
        if (in_sizes[i] == NPIX * 4) unary = (const float*)d_in[i];
        else if (in_sizes[i] == NPIX * 3) image = (const float*)d_in[i];
    }

    cudaFuncSetAttribute(k_crf, cudaFuncAttributeMaxDynamicSharedMemorySize, SMEM_BYTES);

    int sms = 0, occ = 0;
    cudaDeviceGetAttribute(&sms, cudaDevAttrMultiProcessorCount, 0);
    cudaOccupancyMaxActiveBlocksPerMultiprocessor(&occ, k_crf, TPB, SMEM_BYTES);
    if (sms <= 0) sms = 148;
    if (occ <= 0) occ = 1;
    int nb = sms * occ;
    if (nb > 1024) nb = 1024;

    k_crf<<<nb, TPB, SMEM_BYTES>>>(image, (const float4*)unary, (float4*)d_out, nb);
}

// round 17
// speedup vs baseline: 1.1782x; 1.0110x over previous
#include <cuda_runtime.h>

#define WID 512
#define HEI 512
#define NPIX (WID*HEI)
#define RAD 10
#define KS 21
#define TPB 256
#define TSX 32
#define TSY 16
#define TINX 52
#define TINY 36
#define SINP 53                 // padded input tile stride (u64 units; odd -> CF column access)
#define SHP  33                 // padded H-buffer stride (odd -> CF column access)
#define NTX (WID/TSX)           // 16
#define NTY (HEI/TSY)           // 32
#define NTILES (NTX*NTY)        // 512
#define NELEM (TINY*SINP)       // 1908
#define STEPR (TPB/SINP)        // 4
#define STEPC (TPB - STEPR*SINP) // 44

// smem layout (bytes) — overlap-packed per phase
#define OFF_IN0   0                       // u64[36*53] = 15264
#define OFF_GRAY  15264                   // float[36*53] = 7632  (PhaseA)
#define OFF_INB   15264                   // u64 tile (PhaseB second input)
#define OFF_AH0   22896                   // H buffers: u64[36*33] = 9504
#define OFF_AH1   32400
#define OFF_AH2   41904
#define OFF_BH0   30528
#define OFF_BH1   40032
#define SMEM_BYTES 51408

typedef unsigned long long u64;

// ---------------- compile-time weights ----------------
constexpr double cexp(double x) {
    double y = x / 16.0, s = 1.0, t = 1.0;
    for (int i = 1; i < 40; i++) { t *= y / (double)i; s += t; }
    s = s * s; s = s * s; s = s * s; s = s * s;
    return s;
}
constexpr double wgd(int t) { double d = (double)(t - RAD); return cexp(-d * d / 12.5); }
constexpr double wdd(int t) { double d = (double)(t - RAD); return cexp(-d * d * 9.0 / 200.0); }
constexpr double sumw(int wh) { double s = 0; for (int i = 0; i < KS; i++) s += (wh ? wgd(i) : wdd(i)); return s; }
constexpr double pref(int wh, int n) { double s = 0; for (int i = 0; i < n; i++) s += (wh ? wgd(i) : wdd(i)); return s; }

constexpr float SD_F    = (float)sumw(0);
constexpr float SG_F    = (float)sumw(1);
constexpr float SDINV_F = (float)(1.0 / (sumw(0) * sumw(0)));

#define TAPLIST(F) F(0) F(1) F(2) F(3) F(4) F(5) F(6) F(7) F(8) F(9) F(10) \
                   F(11) F(12) F(13) F(14) F(15) F(16) F(17) F(18) F(19) F(20)
#define DWG(i) constexpr float WG_##i = (float)wgd(i);
#define DWD(i) constexpr float WD_##i = (float)wdd(i);
TAPLIST(DWG)
TAPLIST(DWD)

__device__ __forceinline__ float wG(int t) {
    switch (t) {
#define CWG(i) case i: return WG_##i;
        TAPLIST(CWG)
#undef CWG
    }
    return 0.f;
}
__device__ __forceinline__ float wD(int t) {
    switch (t) {
#define CWD(i) case i: return WD_##i;
        TAPLIST(CWD)
#undef CWD
    }
    return 0.f;
}

__constant__ float c_pD[11] = {
    (float)pref(0,0),(float)pref(0,1),(float)pref(0,2),(float)pref(0,3),(float)pref(0,4),
    (float)pref(0,5),(float)pref(0,6),(float)pref(0,7),(float)pref(0,8),(float)pref(0,9),
    (float)pref(0,10)
};
__constant__ float c_pG[11] = {
    (float)pref(1,0),(float)pref(1,1),(float)pref(1,2),(float)pref(1,3),(float)pref(1,4),
    (float)pref(1,5),(float)pref(1,6),(float)pref(1,7),(float)pref(1,8),(float)pref(1,9),
    (float)pref(1,10)
};

__device__ __forceinline__ float hsD(int x) {
    float s = SD_F;
    if (x < RAD) s -= c_pD[RAD - x];
    if (x > WID - 1 - RAD) s -= c_pD[x - (WID - 1 - RAD)];
    return s;
}
__device__ __forceinline__ float hsG(int x) {
    float s = SG_F;
    if (x < RAD) s -= c_pG[RAD - x];
    if (x > WID - 1 - RAD) s -= c_pG[x - (WID - 1 - RAD)];
    return s;
}

// ---------------- packed f32x2 helpers ----------------
__device__ __forceinline__ u64 pk2(float x, float y) {
    u64 r; asm("mov.b64 %0,{%1,%2};" : "=l"(r) : "f"(x), "f"(y)); return r;
}
__device__ __forceinline__ float2 up2(u64 v) {
    float2 o; asm("mov.b64 {%0,%1},%2;" : "=f"(o.x), "=f"(o.y) : "l"(v)); return o;
}
__device__ __forceinline__ void fma2(u64& d, u64 a, u64 b) {
    asm("fma.rn.f32x2 %0,%1,%2,%0;" : "+l"(d) : "l"(a), "l"(b));
}
__device__ __forceinline__ u64 mul2(u64 a, u64 b) {
    u64 r; asm("mul.rn.f32x2 %0,%1,%2;" : "=l"(r) : "l"(a), "l"(b)); return r;
}
__device__ __forceinline__ u64 wpc(float w) {   // (w,w) pair; constant-folds after unroll
    unsigned u = __float_as_uint(w);
    return ((u64)u << 32) | (u64)u;
}

// ---------------- static device planes ----------------
__device__ float g_gray[NPIX], g_mI[NPIX], g_iv[NPIX], g_ibn[NPIX], g_spc[NPIX];
__device__ u64 g_ab1[NPIX];
__device__ u64 g_Qxy[NPIX], g_Qzw[NPIX];
__device__ u64 g_a0[NPIX], g_a1p[NPIX], g_b0[NPIX], g_b1p[NPIX], g_sp0[NPIX], g_sp1[NPIX];

// ---------------- grid barrier (monotonic arrivals; no reset) ----------------
__device__ unsigned g_count = 0;
__device__ unsigned g_gen   = 0;

// CG-style grid barrier: one elected thread per block carries the
// release/acquire fences. Arrival counter is monotonic (target =
// (gen+1)*nb) so the release path has no reset store -> no reset/publish
// ordering hazard and one less serialized op. Wraparound-safe (equality).
__device__ __forceinline__ unsigned gridbar(unsigned gen, unsigned nb) {
    unsigned next = gen + 1;
    __syncthreads();
    if (threadIdx.x == 0) {
        __threadfence();   // release (block's prior writes -> L2)
        if (atomicAdd(&g_count, 1u) == next * nb - 1u) {
            atomicExch(&g_gen, next);
        } else {
            volatile unsigned* ph = &g_gen;
            while (*ph != next) { __nanosleep(128); }
        }
        __threadfence();   // acquire (invalidate this SM's L1)
    }
    __syncthreads();
    return next;
}

__device__ __forceinline__ float4 softmax4(float4 z) {
    float m = fmaxf(fmaxf(z.x, z.y), fmaxf(z.z, z.w));
    float ex = __expf(z.x - m), ey = __expf(z.y - m);
    float ez = __expf(z.z - m), ew = __expf(z.w - m);
    float inv = 1.f / (ex + ey + ez + ew);
    return make_float4(ex * inv, ey * inv, ez * inv, ew * inv);
}

// tile loader with incremental row/col tracking (one division at entry)
__device__ __forceinline__ void load_tile(u64* dst, const u64* src,
                                          int X0, int Y0, int tid) {
    int r = tid / SINP, c = tid - (tid / SINP) * SINP;
    for (int s = tid; s < NELEM; s += TPB) {
        int gx = X0 + c - RAD, gy = Y0 + r - RAD;
        u64 v = 0ULL;
        if (c < TINX && (unsigned)gx < WID && (unsigned)gy < HEI) v = src[gy * WID + gx];
        dst[s] = v;
        r += STEPR; c += STEPC;
        if (c >= SINP) { c -= SINP; r++; }
    }
}

// H task geometry: tasks 0..7 = column chunk (xb=task*4), rows = lane (0..31).
// task 8 = tail rows 32..35: lane = (row-32)*8 + chunk.
__device__ __forceinline__ void htask_geom(int task, int lane, int& row, int& xb) {
    if (task < 8) { row = lane;              xb = task * 4; }
    else          { row = 32 + (lane >> 3);  xb = (lane & 7) * 4; }
}

// ---------------- the persistent kernel ----------------
__global__ void __launch_bounds__(TPB, 4)
k_crf(const float* __restrict__ img, const float4* __restrict__ unary,
      float4* __restrict__ dout, int nb) {
    extern __shared__ char dsm[];
    u64*   sIn  = (u64*)(dsm + OFF_IN0);
    float* sg   = (float*)(dsm + OFF_GRAY);
    u64*   sInB = (u64*)(dsm + OFF_INB);
    u64*   aH0  = (u64*)(dsm + OFF_AH0);
    u64*   aH1  = (u64*)(dsm + OFF_AH1);
    u64*   aH2  = (u64*)(dsm + OFF_AH2);
    u64*   bH0  = (u64*)(dsm + OFF_BH0);
    u64*   bH1  = (u64*)(dsm + OFF_BH1);

    const int tid  = threadIdx.x;
    const int wid  = tid >> 5;
    const int lane = tid & 31;
    const int gid  = blockIdx.x * TPB + tid;
    const int T    = nb * TPB;

    unsigned gen;
    {
        __shared__ unsigned sgen;
        if (tid == 0) sgen = *(volatile unsigned*)&g_gen;
        __syncthreads();
        gen = sgen;
    }

    // ---- P0: grayscale + Q0 = softmax(-unary) ----
    for (int i = gid; i < NPIX; i += T) {
        float r = img[3 * i], gg = img[3 * i + 1], b = img[3 * i + 2];
        g_gray[i] = 0.2989f * r + 0.5870f * gg + 0.1140f * b;
        float4 u = unary[i];
        float4 q = softmax4(make_float4(-u.x, -u.y, -u.z, -u.w));
        g_Qxy[i] = pk2(q.x, q.y);
        g_Qzw[i] = pk2(q.z, q.w);
    }
    gen = gridbar(gen, nb);

    // ---- PreA: conv2D of (gray, gray^2) -> mI, iv, (a1,b1) ----
    for (int t = blockIdx.x; t < NTILES; t += nb) {
        int X0 = (t & (NTX - 1)) * TSX, Y0 = (t >> 4) * TSY;
        {
            int r = tid / SINP, c = tid - (tid / SINP) * SINP;
            for (int s = tid; s < NELEM; s += TPB) {
                int gx = X0 + c - RAD, gy = Y0 + r - RAD;
                u64 v = 0ULL;
                if (c < TINX && (unsigned)gx < WID && (unsigned)gy < HEI) {
                    float gv = g_gray[gy * WID + gx];
                    v = pk2(gv, gv * gv);
                }
                sIn[s] = v;
                r += STEPR; c += STEPC;
                if (c >= SINP) { c -= SINP; r++; }
            }
        }
        __syncthreads();
        for (int task = wid; task < 9; task += 8) {
            int row, xb; htask_geom(task, lane, row, xb);
            u64 a[4] = {0,0,0,0};
            const u64* rw = sIn + row * SINP + xb;
#pragma unroll
            for (int tt = 0; tt < 24; tt++) {
                u64 v = rw[tt];
#pragma unroll
                for (int m = 0; m < 4; m++) {
                    int w = tt - m;
                    if (w >= 0 && w < KS) fma2(a[m], v, wpc(wD(w)));
                }
            }
#pragma unroll
            for (int m = 0; m < 4; m++) aH0[row * SHP + xb + m] = a[m];
        }
        __syncthreads();
        if (wid < 4) {
            int py0 = wid * 4;
            u64 A[4] = {0,0,0,0};
#pragma unroll
            for (int j = 0; j < 24; j++) {
                u64 v = aH0[(py0 + j) * SHP + lane];
#pragma unroll
                for (int m = 0; m < 4; m++) {
                    int w = j - m;
                    if (w >= 0 && w < KS) fma2(A[m], v, wpc(wD(w)));
                }
            }
            float hdx = hsD(X0 + lane);
#pragma unroll
            for (int m = 0; m < 4; m++) {
                int py = py0 + m, gy = Y0 + py, idx = gy * WID + X0 + lane;
                float2 c = up2(A[m]);
                float g = up2(sIn[(py + RAD) * SINP + lane + RAD]).x;
                float mI  = (c.x - g) * SDINV_F;
                float mII = (c.y - g * g) * SDINV_F;
                float mp1 = (hdx * hsD(gy) - 1.f) * SDINV_F;
                float var = mII - mI * mI;
                float iv  = 1.f / (var + 1e-4f);
                float a1  = mI * (1.f - mp1) * iv;
                float b1  = mp1 - a1 * mI;
                g_mI[idx] = mI; g_iv[idx] = iv; g_ab1[idx] = pk2(a1, b1);
            }
        }
        __syncthreads();
    }
    gen = gridbar(gen, nb);

    // ---- PreB: conv2D of (a1,b1) -> ibn, spc ----
    for (int t = blockIdx.x; t < NTILES; t += nb) {
        int X0 = (t & (NTX - 1)) * TSX, Y0 = (t >> 4) * TSY;
        load_tile(sIn, g_ab1, X0, Y0, tid);
        __syncthreads();
        for (int task = wid; task < 9; task += 8) {
            int row, xb; htask_geom(task, lane, row, xb);
            u64 a[4] = {0,0,0,0};
            const u64* rw = sIn + row * SINP + xb;
#pragma unroll
            for (int tt = 0; tt < 24; tt++) {
                u64 v = rw[tt];
#pragma unroll
                for (int m = 0; m < 4; m++) {
                    int w = tt - m;
                    if (w >= 0 && w < KS) fma2(a[m], v, wpc(wD(w)));
                }
            }
#pragma unroll
            for (int m = 0; m < 4; m++) aH0[row * SHP + xb + m] = a[m];
        }
        __syncthreads();
        if (wid < 4) {
            int py0 = wid * 4;
            u64 A[4] = {0,0,0,0};
#pragma unroll
            for (int j = 0; j < 24; j++) {
                u64 v = aH0[(py0 + j) * SHP + lane];
#pragma unroll
                for (int m = 0; m < 4; m++) {
                    int w = j - m;
                    if (w >= 0 && w < KS) fma2(A[m], v, wpc(wD(w)));
                }
            }
            float hgx = hsG(X0 + lane);
#pragma unroll
            for (int m = 0; m < 4; m++) {
                int py = py0 + m, gy = Y0 + py, idx = gy * WID + X0 + lane;
                float2 c  = up2(A[m]);
                float2 ab = up2(sIn[(py + RAD) * SINP + lane + RAD]);
                float g = g_gray[idx];
                float gfa = (c.x - ab.x) * SDINV_F;
                float gfb = (c.y - ab.y) * SDINV_F;
                g_ibn[idx] = 10.f / (gfa * g + gfb);
                g_spc[idx] = 3.f / (hgx * hsG(gy) - 1.f);
            }
        }
        __syncthreads();
    }
    gen = gridbar(gen, nb);

    // ---- 5 mean-field iterations: 2 tiled phases each ----
    for (int it = 0; it < 5; it++) {
        // ===== PhaseA: conv2D(Q)x{G,D} + conv2D(grayQ)xD -> a,b,sp =====
        for (int t = blockIdx.x; t < NTILES; t += nb) {
            int X0 = (t & (NTX - 1)) * TSX, Y0 = (t >> 4) * TSY;
            {
                int r = tid / SINP, c = tid - (tid / SINP) * SINP;
                for (int s = tid; s < NELEM; s += TPB) {
                    int gx = X0 + c - RAD, gy = Y0 + r - RAD;
                    float v = 0.f;
                    if (c < TINX && (unsigned)gx < WID && (unsigned)gy < HEI) v = g_gray[gy * WID + gx];
                    sg[s] = v;
                    r += STEPR; c += STEPC;
                    if (c >= SINP) { c -= SINP; r++; }
                }
            }
            for (int h = 0; h < 2; h++) {
                load_tile(sIn, h ? g_Qzw : g_Qxy, X0, Y0, tid);
                __syncthreads();
                for (int task = wid; task < 9; task += 8) {
                    int row, xb; htask_geom(task, lane, row, xb);
                    u64 aD[4] = {0,0,0,0}, aG[4] = {0,0,0,0}, aI[4] = {0,0,0,0};
                    const u64*  rw = sIn + row * SINP + xb;
                    const float* rg = sg + row * SINP + xb;
#pragma unroll
                    for (int tt = 0; tt < 24; tt++) {
                        u64 v = rw[tt];
                        float gf = rg[tt];
                        u64 wv = mul2(v, pk2(gf, gf));
#pragma unroll
                        for (int m = 0; m < 4; m++) {
                            int w = tt - m;
                            if (w >= 0 && w < KS) {
                                fma2(aD[m], v,  wpc(wD(w)));
                                fma2(aG[m], v,  wpc(wG(w)));
                                fma2(aI[m], wv, wpc(wD(w)));
                            }
                        }
                    }
#pragma unroll
                    for (int m = 0; m < 4; m++) {
                        aH0[row * SHP + xb + m] = aD[m];
                        aH1[row * SHP + xb + m] = aG[m];
                        aH2[row * SHP + xb + m] = aI[m];
                    }
                }
                __syncthreads();
                if (wid < 4) {
                    int py0 = wid * 4;
                    u64 AD[4] = {0,0,0,0}, AG[4] = {0,0,0,0}, AI[4] = {0,0,0,0};
#pragma unroll
                    for (int j = 0; j < 24; j++) {
                        u64 v0 = aH0[(py0 + j) * SHP + lane];
                        u64 v1 = aH1[(py0 + j) * SHP + lane];
                        u64 v2 = aH2[(py0 + j) * SHP + lane];
#pragma unroll
                        for (int m = 0; m < 4; m++) {
                            int w = j - m;
                            if (w >= 0 && w < KS) {
                                fma2(AD[m], v0, wpc(wD(w)));
                                fma2(AG[m], v1, wpc(wG(w)));
                                fma2(AI[m], v2, wpc(wD(w)));
                            }
                        }
                    }
#pragma unroll
                    for (int m = 0; m < 4; m++) {
                        int py = py0 + m, idx = (Y0 + py) * WID + X0 + lane;
                        float2 q = up2(sIn[(py + RAD) * SINP + lane + RAD]);
                        float g = sg[(py + RAD) * SINP + lane + RAD];
                        float2 ad = up2(AD[m]), ag = up2(AG[m]), ai = up2(AI[m]);
                        float mI = g_mI[idx], iv = g_iv[idx], spc = g_spc[idx];
                        float spx = (ag.x - q.x) * spc,         spy = (ag.y - q.y) * spc;
                        float mpx = (ad.x - q.x) * SDINV_F,     mpy = (ad.y - q.y) * SDINV_F;
                        float mix = (ai.x - g * q.x) * SDINV_F, miy = (ai.y - g * q.y) * SDINV_F;
                        float ax = (mix - mI * mpx) * iv,       ay = (miy - mI * mpy) * iv;
                        float bx = mpx - ax * mI,               by = mpy - ay * mI;
                        if (h == 0) {
                            g_a0[idx]  = pk2(ax, ay);
                            g_b0[idx]  = pk2(bx, by);
                            g_sp0[idx] = pk2(spx, spy);
                        } else {
                            g_a1p[idx] = pk2(ax, ay);
                            g_b1p[idx] = pk2(bx, by);
                            g_sp1[idx] = pk2(spx, spy);
                        }
                    }
                }
                __syncthreads();
            }
        }
        gen = gridbar(gen, nb);

        // ===== PhaseB: conv2D(a,b) + message + softmax -> Q / dout =====
        for (int t = blockIdx.x; t < NTILES; t += nb) {
            int X0 = (t & (NTX - 1)) * TSX, Y0 = (t >> 4) * TSY;
            float z0[8];
            for (int h = 0; h < 2; h++) {
                load_tile(sIn,  h ? g_a1p : g_a0, X0, Y0, tid);
                load_tile(sInB, h ? g_b1p : g_b0, X0, Y0, tid);
                __syncthreads();
                for (int task = wid; task < 9; task += 8) {
                    int row, xb; htask_geom(task, lane, row, xb);
                    u64 aA[4] = {0,0,0,0}, aB[4] = {0,0,0,0};
                    const u64* rwA = sIn  + row * SINP + xb;
                    const u64* rwB = sInB + row * SINP + xb;
#pragma unroll
                    for (int tt = 0; tt < 24; tt++) {
                        u64 vA = rwA[tt], vB = rwB[tt];
#pragma unroll
                        for (int m = 0; m < 4; m++) {
                            int w = tt - m;
                            if (w >= 0 && w < KS) {
                                fma2(aA[m], vA, wpc(wD(w)));
                                fma2(aB[m], vB, wpc(wD(w)));
                            }
                        }
                    }
#pragma unroll
                    for (int m = 0; m < 4; m++) {
                        bH0[row * SHP + xb + m] = aA[m];
                        bH1[row * SHP + xb + m] = aB[m];
                    }
                }
                __syncthreads();
                if (wid < 4) {
                    int py0 = wid * 4;
                    u64 AA[4] = {0,0,0,0}, AB[4] = {0,0,0,0};
#pragma unroll
                    for (int j = 0; j < 24; j++) {
                        u64 v0 = bH0[(py0 + j) * SHP + lane];
                        u64 v1 = bH1[(py0 + j) * SHP + lane];
#pragma unroll
                        for (int m = 0; m < 4; m++) {
                            int w = j - m;
                            if (w >= 0 && w < KS) {
                                fma2(AA[m], v0, wpc(wD(w)));
                                fma2(AB[m], v1, wpc(wD(w)));
                            }
                        }
                    }
#pragma unroll
                    for (int m = 0; m < 4; m++) {
                        int py = py0 + m, idx = (Y0 + py) * WID + X0 + lane;
                        float2 ac = up2(sIn [(py + RAD) * SINP + lane + RAD]);
                        float2 bc = up2(sInB[(py + RAD) * SINP + lane + RAD]);
                        float2 aa = up2(AA[m]), ab = up2(AB[m]);
                        float2 sp = up2(h ? g_sp1[idx] : g_sp0[idx]);
                        float ibn = g_ibn[idx], g = g_gray[idx];
                        float2 uu = *((const float2*)unary + 2 * idx + h);
                        float zx = sp.x + ((aa.x - ac.x) * SDINV_F * g
                                         + (ab.x - bc.x) * SDINV_F) * ibn - uu.x;
                        float zy = sp.y + ((aa.y - ac.y) * SDINV_F * g
                                         + (ab.y - bc.y) * SDINV_F) * ibn - uu.y;
                        if (h == 0) {
                            z0[2*m] = zx; z0[2*m+1] = zy;
                        } else {
                            float4 q = softmax4(make_float4(z0[2*m], z0[2*m+1], zx, zy));
                            if (it == 4) {
                                dout[idx] = q;
                            } else {
                                g_Qxy[idx] = pk2(q.x, q.y);
                                g_Qzw[idx] = pk2(q.z, q.w);
                            }
                        }
                    }
                }
                __syncthreads();
            }
        }
        if (it < 4) gen = gridbar(gen, nb);
    }
}

// ---------------- launch ----------------
extern "C" void kernel_launch(void* const* d_in, const int* in_sizes, int n_in,
                              void* d_out, int out_size) {
    const float* unary = nullptr;
    const float* image = nullptr;
    for (int i = 0; i < n_in; i++) {
        if (in_sizes[i] == NPIX * 4) unary = (const float*)d_in[i];
        else if (in_sizes[i] == NPIX * 3) image = (const float*)d_in[i];
    }

    cudaFuncSetAttribute(k_crf, cudaFuncAttributeMaxDynamicSharedMemorySize, SMEM_BYTES);

    int sms = 0, occ = 0;
    cudaDeviceGetAttribute(&sms, cudaDevAttrMultiProcessorCount, 0);
    cudaOccupancyMaxActiveBlocksPerMultiprocessor(&occ, k_crf, TPB, SMEM_BYTES);
    if (sms <= 0) sms = 148;
    if (occ <= 0) occ = 1;
    int nb = sms * occ;
    if (nb > 1024) nb = 1024;

    k_crf<<<nb, TPB, SMEM_BYTES>>>(image, (const float4*)unary, (float4*)d_out, nb);
}